// round 5
// baseline (speedup 1.0000x reference)
#include <cuda_runtime.h>
#include <math.h>

// Problem constants
#define B_   2
#define G_   8
#define L_   576
#define D_   32
#define NTOK 9216           // B*G*L
#define NT32 (NTOK * 32)
#define NTILES 144
#define LOG2E 1.4426950408889634f

// Scratch (allocation-free rule: __device__ globals)
__device__ float    g_Q[NT32];
__device__ unsigned g_Khi[NT32];    // tf32 hi, k-permuted columns
__device__ unsigned g_Klo[NT32];    // tf32 lo, k-permuted columns
__device__ unsigned g_VtT[NT32];    // tf32 V, [tile][feat 32][key 64] permuted keys
__device__ float    g_qnorm2[NTOK];
__device__ int      g_kmax2;        // bits of max ||k||^2 (atomicMax, monotone)

// ---------------------------------------------------------------------------
// tf32 helpers
// ---------------------------------------------------------------------------
__device__ __forceinline__ unsigned f2tf32(float x) {
    unsigned r;
    asm("cvt.rna.tf32.f32 %0, %1;" : "=r"(r) : "f"(x));
    return r;
}
__device__ __forceinline__ void split_tf32(float x, unsigned& hi, unsigned& lo) {
    hi = f2tf32(x);
    lo = f2tf32(x - __uint_as_float(hi));
}
__device__ __forceinline__ void mma_tf32(float c[4], const unsigned a[4],
                                         unsigned b0, unsigned b1) {
    asm volatile(
        "mma.sync.aligned.m16n8k8.row.col.f32.tf32.tf32.f32 "
        "{%0,%1,%2,%3}, {%4,%5,%6,%7}, {%8,%9}, {%0,%1,%2,%3};"
        : "+f"(c[0]), "+f"(c[1]), "+f"(c[2]), "+f"(c[3])
        : "r"(a[0]), "r"(a[1]), "r"(a[2]), "r"(a[3]), "r"(b0), "r"(b1));
}

// ---------------------------------------------------------------------------
// Kernel 1: grouped 1x1 conv -> Q (pre-scaled) + row norms,
//           K (+PE) pre-split tf32 hi/lo (k-permuted), V pre-converted tf32
//           transposed per attention tile. Also global max ||k||^2.
// ---------------------------------------------------------------------------
__global__ void __launch_bounds__(256) qkv_kernel(
    const float* __restrict__ x,
    const float* __restrict__ wq,
    const float* __restrict__ wk,
    const float* __restrict__ wv)
{
    const int bh = blockIdx.x;           // 0..15
    const int b  = bh >> 3;
    const int h  = bh & 7;
    const int l0 = blockIdx.y * 64;      // 0..512 step 64

    __shared__ float xs[32][64];

    const int tid = threadIdx.x;
    const float* xbase = x + ((size_t)(b * 256 + h * 32)) * L_ + l0;
    for (int i = tid; i < 32 * 64; i += 256) {
        int dd = i >> 6, ll = i & 63;
        xs[dd][ll] = xbase[dd * L_ + ll];
    }
    __syncthreads();

    const int o    = tid & 31;
    const int lg   = (tid >> 5) * 8;
    const int c    = h * 32 + o;
    const int nbase = bh * L_ + l0 + lg;
    // k-permuted column for feature o: pairs (t, t+4) adjacent within 8-group
    const int p_o  = (o & 24) + 2 * (o & 3) + ((o >> 2) & 1);
    const int tile = bh * 9 + blockIdx.y;

    #pragma unroll
    for (int m = 0; m < 3; m++) {
        const float* w = (m == 0 ? wq : (m == 1 ? wk : wv)) + (size_t)c * 32;
        float acc[8];
        #pragma unroll
        for (int e = 0; e < 8; e++) acc[e] = 0.f;

        #pragma unroll
        for (int dd = 0; dd < 32; dd++) {
            float wv_ = w[dd];
            float4 a  = *(const float4*)&xs[dd][lg];
            float4 a2 = *(const float4*)&xs[dd][lg + 4];
            acc[0] = fmaf(wv_, a.x,  acc[0]);
            acc[1] = fmaf(wv_, a.y,  acc[1]);
            acc[2] = fmaf(wv_, a.z,  acc[2]);
            acc[3] = fmaf(wv_, a.w,  acc[3]);
            acc[4] = fmaf(wv_, a2.x, acc[4]);
            acc[5] = fmaf(wv_, a2.y, acc[5]);
            acc[6] = fmaf(wv_, a2.z, acc[6]);
            acc[7] = fmaf(wv_, a2.w, acc[7]);
        }

        if (m == 0) {
            const float scale = 0.17677669529663688f;  // 1/sqrt(32)
            #pragma unroll
            for (int e = 0; e < 8; e++) {
                float val = acc[e] * scale;
                g_Q[(size_t)(nbase + e) * 32 + o] = val;
                float sq = val * val;
                #pragma unroll
                for (int off = 16; off > 0; off >>= 1)
                    sq += __shfl_xor_sync(0xffffffffu, sq, off);
                if (o == 0) g_qnorm2[nbase + e] = sq;
            }
        } else if (m == 1) {
            int ieven = c & ~1;
            float t = (-9.210340371976184f * (float)ieven) * (1.0f / 256.0f);
            float invf = (float)exp((double)t);
            float kmax_local = 0.f;
            #pragma unroll
            for (int e = 0; e < 8; e++) {
                float ang = invf * (float)(l0 + lg + e);
                float pe = (c & 1) ? (float)cos((double)ang)
                                   : (float)sin((double)ang);
                float val = acc[e] + pe;
                unsigned hi, lo;
                split_tf32(val, hi, lo);
                g_Khi[(size_t)(nbase + e) * 32 + p_o] = hi;
                g_Klo[(size_t)(nbase + e) * 32 + p_o] = lo;
                float sq = val * val;
                #pragma unroll
                for (int off = 16; off > 0; off >>= 1)
                    sq += __shfl_xor_sync(0xffffffffu, sq, off);
                kmax_local = fmaxf(kmax_local, sq);
            }
            if (o == 0) atomicMax(&g_kmax2, __float_as_int(kmax_local));
        } else {
            // V transposed per 64-token tile: [tile][feat o][key lg+perm(e)]
            unsigned* vbase = g_VtT + (size_t)tile * 2048 + o * 64 + lg;
            #pragma unroll
            for (int e = 0; e < 8; e++)
                vbase[2 * (e & 3) + (e >> 2)] = f2tf32(acc[e]);
        }
    }
}

// ---------------------------------------------------------------------------
// Kernel 2: flash attention, static-max softmax, tf32 MMA.
// 144 blocks x 256 threads (8 warps). All conversions precomputed.
// K/V triple-buffered (pure LDG->STS prefetch), Ps double-buffered,
// ONE __syncthreads per tile. No per-tile stats exchange.
// ---------------------------------------------------------------------------
#define KSTR 36
#define VSTR 68
#define PSTR 68
#define KBUF 2304   // 64*36
#define VBUF 2176   // 32*68
#define PBUF 4352   // 64*68
#define SMEM_UINTS (3*KBUF*2 + 3*VBUF + 2*PBUF + 128)
#define SMEM_BYTES (SMEM_UINTS * 4)

__global__ void __launch_bounds__(256) attn_kernel(float* __restrict__ out)
{
    extern __shared__ unsigned smem[];
    unsigned* Khs = smem;                 // 3 * 2304
    unsigned* Kls = Khs + 3 * KBUF;
    unsigned* Vts = Kls + 3 * KBUF;       // 3 * 2176, [feat][key]
    unsigned* Pss = Vts + 3 * VBUF;       // 2 * 4352
    float*    red = (float*)(Pss + 2 * PBUF);  // 128

    const int tid  = threadIdx.x;
    const int lane = tid & 31;
    const int w    = tid >> 5;
    const int mw   = w >> 1, nw = w & 1;
    const int g    = lane >> 2, t = lane & 3;
    const int q0   = blockIdx.x * 64;
    const int r0   = 16 * mw + g;

    const int pr0 = tid >> 3;            // 0..31
    const int pc  = (tid & 7) * 4;

    // ---- stage Q (via Ps buffer as float), build split A-frags ----
    float* Qstage = (float*)Pss;
    for (int i = tid; i < 512; i += 256) {
        int r = i >> 3, c = (i & 7) * 4;
        *(float4*)&Qstage[r * PSTR + c] =
            *(const float4*)&g_Q[(size_t)(q0 + r) * 32 + c];
    }
    __syncthreads();

    unsigned qh[4][4], ql[4][4];
    #pragma unroll
    for (int ks = 0; ks < 4; ks++) {
        split_tf32(Qstage[r0 * PSTR + 8 * ks + t],           qh[ks][0], ql[ks][0]);
        split_tf32(Qstage[(r0 + 8) * PSTR + 8 * ks + t],     qh[ks][1], ql[ks][1]);
        split_tf32(Qstage[r0 * PSTR + 8 * ks + t + 4],       qh[ks][2], ql[ks][2]);
        split_tf32(Qstage[(r0 + 8) * PSTR + 8 * ks + t + 4], qh[ks][3], ql[ks][3]);
    }

    // static row bounds: M = ||q|| * max||k||, pre-multiplied by log2(e)
    const float kmax2 = __int_as_float(g_kmax2);
    const float Ml0 = sqrtf(g_qnorm2[q0 + r0]     * kmax2) * LOG2E;
    const float Ml1 = sqrtf(g_qnorm2[q0 + r0 + 8] * kmax2) * LOG2E;

    __syncthreads();   // everyone done reading Qstage before P overwrites

    // ---- prefetch tile 0 into buffer 0 ----
    #pragma unroll
    for (int it = 0; it < 2; it++) {
        int r = pr0 + 32 * it;
        *(uint4*)&Khs[r * KSTR + pc] = *(const uint4*)&g_Khi[(size_t)r * 32 + pc];
        *(uint4*)&Kls[r * KSTR + pc] = *(const uint4*)&g_Klo[(size_t)r * 32 + pc];
    }
    {
        const unsigned* vsrc = g_VtT + tid * 8;   // tile 0: [feat][key] flat
        int f = tid >> 3, c0 = (tid & 7) * 8;
        *(uint4*)&Vts[f * VSTR + c0]     = *(const uint4*)&vsrc[0];
        *(uint4*)&Vts[f * VSTR + c0 + 4] = *(const uint4*)&vsrc[4];
    }
    __syncthreads();

    float o[2][4];
    #pragma unroll
    for (int i = 0; i < 2; i++)
        #pragma unroll
        for (int j = 0; j < 4; j++) o[i][j] = 0.f;
    float lp0 = 0.f, lp1 = 0.f;

    int cur = 0, nxt = 1;
    for (int tt = 0; tt < NTILES; tt++) {
        const unsigned* KhiC = Khs + cur * KBUF;
        const unsigned* KloC = Kls + cur * KBUF;
        const unsigned* VtC  = Vts + cur * VBUF;
        unsigned* Psb = Pss + (tt & 1) * PBUF;

        // ---- issue LDG for tile tt+1 ----
        uint4 nkh[2], nkl[2], nv[2];
        const bool has_next = (tt + 1 < NTILES);
        if (has_next) {
            size_t kbase = (size_t)(tt + 1) * 64 * 32;
            #pragma unroll
            for (int it = 0; it < 2; it++) {
                size_t idx = kbase + (size_t)(pr0 + 32 * it) * 32 + pc;
                nkh[it] = *(const uint4*)&g_Khi[idx];
                nkl[it] = *(const uint4*)&g_Klo[idx];
            }
            const unsigned* vsrc = g_VtT + (size_t)(tt + 1) * 2048 + tid * 8;
            nv[0] = *(const uint4*)&vsrc[0];
            nv[1] = *(const uint4*)&vsrc[4];
        }

        // ---- S = Q K^T, 3-pass split tf32 ----
        float S[4][4];
        #pragma unroll
        for (int i = 0; i < 4; i++)
            #pragma unroll
            for (int j = 0; j < 4; j++) S[i][j] = 0.f;

        #pragma unroll
        for (int ks = 0; ks < 4; ks++) {
            #pragma unroll
            for (int nt = 0; nt < 4; nt++) {
                int kn = 32 * nw + 8 * nt + g;
                uint2 bh = *(const uint2*)&KhiC[kn * KSTR + 8 * ks + 2 * t];
                uint2 bl = *(const uint2*)&KloC[kn * KSTR + 8 * ks + 2 * t];
                mma_tf32(S[nt], qh[ks], bh.x, bh.y);
                mma_tf32(S[nt], ql[ks], bh.x, bh.y);
                mma_tf32(S[nt], qh[ks], bl.x, bl.y);
            }
        }

        // ---- store prefetched tile into buffer nxt ----
        if (has_next) {
            unsigned* KhiN = Khs + nxt * KBUF;
            unsigned* KloN = Kls + nxt * KBUF;
            unsigned* VtN  = Vts + nxt * VBUF;
            #pragma unroll
            for (int it = 0; it < 2; it++) {
                int r = pr0 + 32 * it;
                *(uint4*)&KhiN[r * KSTR + pc] = nkh[it];
                *(uint4*)&KloN[r * KSTR + pc] = nkl[it];
            }
            int f = tid >> 3, c0 = (tid & 7) * 8;
            *(uint4*)&VtN[f * VSTR + c0]     = nv[0];
            *(uint4*)&VtN[f * VSTR + c0 + 4] = nv[1];
        }

        // ---- P = exp(S - M) via ex2(S*log2e - Mlog); store tf32 bits ----
        #pragma unroll
        for (int nt = 0; nt < 4; nt++) {
            float p00 = exp2f(fmaf(S[nt][0], LOG2E, -Ml0));
            float p01 = exp2f(fmaf(S[nt][1], LOG2E, -Ml0));
            float p10 = exp2f(fmaf(S[nt][2], LOG2E, -Ml1));
            float p11 = exp2f(fmaf(S[nt][3], LOG2E, -Ml1));
            lp0 += p00 + p01;
            lp1 += p10 + p11;
            int col = 32 * nw + 8 * nt + 2 * t;
            *(uint2*)&Psb[r0 * PSTR + col] =
                make_uint2(f2tf32(p00), f2tf32(p01));
            *(uint2*)&Psb[(r0 + 8) * PSTR + col] =
                make_uint2(f2tf32(p10), f2tf32(p11));
        }

        __syncthreads();   // THE one barrier per tile

        // ---- O += P V, single-pass tf32, bare LDS operands ----
        #pragma unroll
        for (int ks = 0; ks < 8; ks++) {
            unsigned a[4];
            a[0] = Psb[r0 * PSTR + 8 * ks + t];
            a[1] = Psb[(r0 + 8) * PSTR + 8 * ks + t];
            a[2] = Psb[r0 * PSTR + 8 * ks + t + 4];
            a[3] = Psb[(r0 + 8) * PSTR + 8 * ks + t + 4];
            #pragma unroll
            for (int nt2 = 0; nt2 < 2; nt2++) {
                int vn = 16 * nw + 8 * nt2 + g;
                uint2 bv = *(const uint2*)&VtC[vn * VSTR + 8 * ks + 2 * t];
                mma_tf32(o[nt2], a, bv.x, bv.y);
            }
        }

        cur = nxt;
        nxt = (nxt == 2) ? 0 : nxt + 1;
    }

    // ---- reduce l: across t lanes, then across nw warps ----
    #pragma unroll
    for (int off = 1; off < 4; off <<= 1) {
        lp0 += __shfl_xor_sync(0xffffffffu, lp0, off);
        lp1 += __shfl_xor_sync(0xffffffffu, lp1, off);
    }
    if (t == 0) {
        red[nw * 64 + r0]     = lp0;
        red[nw * 64 + r0 + 8] = lp1;
    }
    __syncthreads();
    float inv0 = 1.0f / (red[r0] + red[64 + r0]);
    float inv1 = 1.0f / (red[r0 + 8] + red[64 + r0 + 8]);

    // ---- epilogue: normalize, scatter to NCHW output ----
    int b = q0 / 4608;
    int rem = q0 - b * 4608;
    int h = rem / 576;
    int lp = (rem - h * 576) + 16 * mw + g;
    #pragma unroll
    for (int nt2 = 0; nt2 < 2; nt2++) {
        int f = 16 * nw + 8 * nt2 + 2 * t;
        size_t base = ((size_t)(b * 256 + h * 32 + f)) * 576;
        out[base + lp]           = o[nt2][0] * inv0;
        out[base + 576 + lp]     = o[nt2][1] * inv0;
        out[base + lp + 8]       = o[nt2][2] * inv1;
        out[base + 576 + lp + 8] = o[nt2][3] * inv1;
    }
}

// ---------------------------------------------------------------------------
extern "C" void kernel_launch(void* const* d_in, const int* in_sizes, int n_in,
                              void* d_out, int out_size)
{
    const float* x  = (const float*)d_in[0];
    const float* wq = (const float*)d_in[1];
    const float* wk = (const float*)d_in[2];
    const float* wv = (const float*)d_in[3];
    float* out = (float*)d_out;

    static bool attr_set = false;
    if (!attr_set) {
        cudaFuncSetAttribute(attn_kernel,
                             cudaFuncAttributeMaxDynamicSharedMemorySize,
                             SMEM_BYTES);
        attr_set = true;
    }

    dim3 g1(16, 9);
    qkv_kernel<<<g1, 256>>>(x, wq, wk, wv);
    attn_kernel<<<NTOK / 64, 256, SMEM_BYTES>>>(out);
}

// round 7
// speedup vs baseline: 1.4497x; 1.4497x over previous
#include <cuda_runtime.h>
#include <math.h>

#define B_   2
#define G_   8
#define L_   576
#define D_   32
#define NTOK 9216
#define NT32 (NTOK * 32)
#define NTILES 144
#define LOG2E 1.4426950408889634f

// Scratch (__device__ globals; allocation-free rule)
__device__ float    g_Q[NT32];
__device__ unsigned g_Kq[NT32 * 2];   // [tile][idx16=4t+ks][kn 64][4w: bh0,bh1,bl0,bl1]
__device__ unsigned g_Vp[NT32];       // [tile][kp 32][feat 32] uint2 = (V[key t],V[key t+4])
__device__ float    g_qnorm2[NTOK];
__device__ int      g_kmax2;

__device__ __forceinline__ unsigned f2tf32(float x) {
    unsigned r;
    asm("cvt.rna.tf32.f32 %0, %1;" : "=r"(r) : "f"(x));
    return r;
}
__device__ __forceinline__ void split_tf32(float x, unsigned& hi, unsigned& lo) {
    hi = f2tf32(x);
    lo = f2tf32(x - __uint_as_float(hi));
}
__device__ __forceinline__ void mma_tf32(float c[4], const unsigned a[4],
                                         unsigned b0, unsigned b1) {
    asm volatile(
        "mma.sync.aligned.m16n8k8.row.col.f32.tf32.tf32.f32 "
        "{%0,%1,%2,%3}, {%4,%5,%6,%7}, {%8,%9}, {%0,%1,%2,%3};"
        : "+f"(c[0]), "+f"(c[1]), "+f"(c[2]), "+f"(c[3])
        : "r"(a[0]), "r"(a[1]), "r"(a[2]), "r"(a[3]), "r"(b0), "r"(b1));
}

// ---------------------------------------------------------------------------
// Kernel 1: grouped 1x1 conv. Q scaled + row norms. K(+PE) -> split tf32,
// stored in attn's exact smem image (key order sigma-permuted per 8-block).
// V -> tf32 paired layout. Global max ||k||^2 via atomicMax.
// ---------------------------------------------------------------------------
__global__ void __launch_bounds__(256) qkv_kernel(
    const float* __restrict__ x,
    const float* __restrict__ wq,
    const float* __restrict__ wk,
    const float* __restrict__ wv)
{
    const int bh = blockIdx.x;
    const int b  = bh >> 3;
    const int h  = bh & 7;
    const int l0 = blockIdx.y * 64;

    __shared__ float xs[32][64];

    const int tid = threadIdx.x;
    const float* xbase = x + ((size_t)(b * 256 + h * 32)) * L_ + l0;
    for (int i = tid; i < 32 * 64; i += 256) {
        int dd = i >> 6, ll = i & 63;
        xs[dd][ll] = xbase[dd * L_ + ll];
    }
    __syncthreads();

    const int o    = tid & 31;           // output feature (dim)
    const int lg   = (tid >> 5) * 8;     // 8 local keys
    const int c    = h * 32 + o;
    const int nbase = bh * L_ + l0 + lg;
    const int tile = bh * 9 + blockIdx.y;

    #pragma unroll
    for (int m = 0; m < 3; m++) {
        const float* w = (m == 0 ? wq : (m == 1 ? wk : wv)) + (size_t)c * 32;
        float acc[8];
        #pragma unroll
        for (int e = 0; e < 8; e++) acc[e] = 0.f;

        #pragma unroll
        for (int dd = 0; dd < 32; dd++) {
            float wv_ = w[dd];
            float4 a  = *(const float4*)&xs[dd][lg];
            float4 a2 = *(const float4*)&xs[dd][lg + 4];
            acc[0] = fmaf(wv_, a.x,  acc[0]);
            acc[1] = fmaf(wv_, a.y,  acc[1]);
            acc[2] = fmaf(wv_, a.z,  acc[2]);
            acc[3] = fmaf(wv_, a.w,  acc[3]);
            acc[4] = fmaf(wv_, a2.x, acc[4]);
            acc[5] = fmaf(wv_, a2.y, acc[5]);
            acc[6] = fmaf(wv_, a2.z, acc[6]);
            acc[7] = fmaf(wv_, a2.w, acc[7]);
        }

        if (m == 0) {
            const float scale = 0.17677669529663688f;  // 1/sqrt(32)
            #pragma unroll
            for (int e = 0; e < 8; e++) {
                float val = acc[e] * scale;
                g_Q[(size_t)(nbase + e) * 32 + o] = val;
                float sq = val * val;
                #pragma unroll
                for (int off = 16; off > 0; off >>= 1)
                    sq += __shfl_xor_sync(0xffffffffu, sq, off);
                if (o == 0) g_qnorm2[nbase + e] = sq;
            }
        } else if (m == 1) {
            int ieven = c & ~1;
            float t = (-9.210340371976184f * (float)ieven) * (1.0f / 256.0f);
            float invf = (float)exp((double)t);
            // dim decomposition for B-frag uint4 slot
            const int kt = o & 3, kks = o >> 3, kb = (o >> 2) & 1;
            const int idx16 = 4 * kt + kks;
            float kmax_local = 0.f;
            #pragma unroll
            for (int e = 0; e < 8; e++) {
                int j = lg + e;                      // local key 0..63
                float ang = invf * (float)(l0 + j);
                float pe = (c & 1) ? (float)cos((double)ang)
                                   : (float)sin((double)ang);
                float val = acc[e] + pe;
                unsigned hi, lo;
                split_tf32(val, hi, lo);
                // sigma: key j -> position kn within tile
                int kn = (j & 56) + 2 * (j & 3) + ((j >> 2) & 1);
                size_t wbase = (size_t)tile * 4096 + (size_t)(idx16 * 64 + kn) * 4;
                g_Kq[wbase + kb]     = hi;
                g_Kq[wbase + 2 + kb] = lo;
                float sq = val * val;
                #pragma unroll
                for (int off = 16; off > 0; off >>= 1)
                    sq += __shfl_xor_sync(0xffffffffu, sq, off);
                kmax_local = fmaxf(kmax_local, sq);
            }
            if (o == 0) atomicMax(&g_kmax2, __float_as_int(kmax_local));
        } else {
            #pragma unroll
            for (int e = 0; e < 8; e++) {
                int j = lg + e;
                int kp   = ((j >> 3) << 2) + (j & 3);
                int slot = (j >> 2) & 1;
                g_Vp[(size_t)tile * 2048 + (size_t)(kp * 32 + o) * 2 + slot] =
                    f2tf32(acc[e]);
            }
        }
    }
}

// ---------------------------------------------------------------------------
// Kernel 2: flash attention, static-max softmax, tf32 MMA, P in registers.
// 144 blocks x 256 threads (8 warps = 4mw x 2nw). Warp: 16 q-rows x 32 keys.
// PV split over keys per warp (O additive); O combined across nw at the end.
// K/V double-buffered, ONE __syncthreads per tile.
// ---------------------------------------------------------------------------
#define KSTR  100      // words per kn row: t*24 + ks*4 + w, padded (400B, 16B mult)
#define KBUF  6400     // 64 * 100 words
#define VSTRU 36       // uint2 per kp row; 36 mod 16 == 4 -> conflict-free LDS.64
#define VBUF  2304     // 32 * 36 * 2 words
#define QSTR  36       // multiple of 4: float4 stage stays 16B aligned
#define OFF_K 0
#define OFF_V (2 * KBUF)
#define OFF_Q (OFF_V + 2 * VBUF)
#define OFF_O (OFF_Q + 64 * QSTR)
#define OFF_R (OFF_O + 2048)
#define SMEM_WORDS (OFF_R + 128)
#define SMEM_BYTES (SMEM_WORDS * 4)

__global__ void __launch_bounds__(256) attn_kernel(float* __restrict__ out)
{
    extern __shared__ unsigned smem[];
    unsigned* Ks  = smem + OFF_K;
    unsigned* Vs  = smem + OFF_V;
    float*    Qst = (float*)(smem + OFF_Q);
    float*    Osm = (float*)(smem + OFF_O);
    float*    red = (float*)(smem + OFF_R);

    const int tid  = threadIdx.x;
    const int lane = tid & 31;
    const int w    = tid >> 5;
    const int mw   = w >> 1, nw = w & 1;
    const int g    = lane >> 2, t = lane & 3;
    const int q0   = blockIdx.x * 64;
    const int r0   = 16 * mw + g;

    // ---- stage Q, build register A-frags (hi/lo) ----
    for (int i = tid; i < 512; i += 256) {
        int r = i >> 3, c = (i & 7) * 4;
        *(float4*)&Qst[r * QSTR + c] =
            *(const float4*)&g_Q[(size_t)(q0 + r) * 32 + c];
    }
    __syncthreads();

    unsigned qh[4][4], ql[4][4];
    #pragma unroll
    for (int ks = 0; ks < 4; ks++) {
        split_tf32(Qst[r0 * QSTR + 8 * ks + t],           qh[ks][0], ql[ks][0]);
        split_tf32(Qst[(r0 + 8) * QSTR + 8 * ks + t],     qh[ks][1], ql[ks][1]);
        split_tf32(Qst[r0 * QSTR + 8 * ks + t + 4],       qh[ks][2], ql[ks][2]);
        split_tf32(Qst[(r0 + 8) * QSTR + 8 * ks + t + 4], qh[ks][3], ql[ks][3]);
    }

    const float kmax2 = __int_as_float(g_kmax2);
    const float Ml0 = sqrtf(g_qnorm2[q0 + r0]     * kmax2) * LOG2E;
    const float Ml1 = sqrtf(g_qnorm2[q0 + r0 + 8] * kmax2) * LOG2E;

    // prefetch coordinates
    const int p_kn  = tid & 63;
    const int p_hi6 = tid >> 6;          // 0..3
    const int v_kp0 = tid >> 5;          // kp for j=0; +8 per j
    const int v_ft  = tid & 31;

    // ---- prefetch tile 0 into buffer 0 ----
    #pragma unroll
    for (int j = 0; j < 4; j++) {
        int idx16 = 4 * j + p_hi6;
        uint4 kv = *(const uint4*)&g_Kq[(size_t)(idx16 * 64 + p_kn) * 4];
        int kt = idx16 >> 2, kk = idx16 & 3;
        *(uint4*)&Ks[p_kn * KSTR + kt * 24 + kk * 4] = kv;
        int kp = v_kp0 + 8 * j;
        uint2 vv = *(const uint2*)&g_Vp[(size_t)(kp * 32 + v_ft) * 2];
        *(uint2*)&Vs[(kp * VSTRU + v_ft) * 2] = vv;
    }
    __syncthreads();

    float o[4][4];
    #pragma unroll
    for (int i = 0; i < 4; i++)
        #pragma unroll
        for (int jj = 0; jj < 4; jj++) o[i][jj] = 0.f;
    float lp0 = 0.f, lp1 = 0.f;

    for (int tt = 0; tt < NTILES; tt++) {
        const unsigned* Kc = Ks + (tt & 1) * KBUF;
        const unsigned* Vc = Vs + (tt & 1) * VBUF;
        unsigned* Kn = Ks + ((tt + 1) & 1) * KBUF;
        unsigned* Vn = Vs + ((tt + 1) & 1) * VBUF;

        // ---- LDG tile tt+1 ----
        uint4 nk[4]; uint2 nv[4];
        const bool has_next = (tt + 1 < NTILES);
        if (has_next) {
            size_t kb = (size_t)(tt + 1) * 4096;
            size_t vb = (size_t)(tt + 1) * 2048;
            #pragma unroll
            for (int j = 0; j < 4; j++) {
                int idx16 = 4 * j + p_hi6;
                nk[j] = *(const uint4*)&g_Kq[kb + (size_t)(idx16 * 64 + p_kn) * 4];
                nv[j] = *(const uint2*)&g_Vp[vb + (size_t)((v_kp0 + 8 * j) * 32 + v_ft) * 2];
            }
        }

        // ---- S = Q K^T (3-pass split tf32) ----
        float S[4][4];
        #pragma unroll
        for (int i = 0; i < 4; i++)
            #pragma unroll
            for (int jj = 0; jj < 4; jj++) S[i][jj] = 0.f;

        #pragma unroll
        for (int ks = 0; ks < 4; ks++) {
            #pragma unroll
            for (int nt = 0; nt < 4; nt++) {
                int kn = 32 * nw + 8 * nt + g;
                uint4 bf = *(const uint4*)&Kc[kn * KSTR + t * 24 + ks * 4];
                mma_tf32(S[nt], qh[ks], bf.x, bf.y);
                mma_tf32(S[nt], ql[ks], bf.x, bf.y);
                mma_tf32(S[nt], qh[ks], bf.z, bf.w);
            }
        }

        // ---- P = exp2(S*log2e - M) in registers; accumulate l ----
        float P[4][4];
        #pragma unroll
        for (int nt = 0; nt < 4; nt++) {
            P[nt][0] = exp2f(fmaf(S[nt][0], LOG2E, -Ml0));
            P[nt][1] = exp2f(fmaf(S[nt][1], LOG2E, -Ml0));
            P[nt][2] = exp2f(fmaf(S[nt][2], LOG2E, -Ml1));
            P[nt][3] = exp2f(fmaf(S[nt][3], LOG2E, -Ml1));
            lp0 += P[nt][0] + P[nt][1];
            lp1 += P[nt][2] + P[nt][3];
        }

        // ---- O += P V over this warp's 32 keys (ks = key block = nt of P) ----
        #pragma unroll
        for (int ks = 0; ks < 4; ks++) {
            unsigned a[4];
            a[0] = f2tf32(P[ks][0]);   // row r0,   k=t
            a[1] = f2tf32(P[ks][2]);   // row r0+8, k=t
            a[2] = f2tf32(P[ks][1]);   // row r0,   k=t+4
            a[3] = f2tf32(P[ks][3]);   // row r0+8, k=t+4
            int kp = (4 * nw + ks) * 4 + t;
            #pragma unroll
            for (int nt2 = 0; nt2 < 4; nt2++) {
                uint2 bv = *(const uint2*)&Vc[(kp * VSTRU + 8 * nt2 + g) * 2];
                mma_tf32(o[nt2], a, bv.x, bv.y);
            }
        }

        // ---- STS tile tt+1 ----
        if (has_next) {
            #pragma unroll
            for (int j = 0; j < 4; j++) {
                int idx16 = 4 * j + p_hi6;
                int kt = idx16 >> 2, kk = idx16 & 3;
                *(uint4*)&Kn[p_kn * KSTR + kt * 24 + kk * 4] = nk[j];
                int kp = v_kp0 + 8 * j;
                *(uint2*)&Vn[(kp * VSTRU + v_ft) * 2] = nv[j];
            }
        }
        __syncthreads();   // the one barrier per tile
    }

    // ---- l reduction: t-lanes, then nw warps via smem ----
    #pragma unroll
    for (int off = 1; off < 4; off <<= 1) {
        lp0 += __shfl_xor_sync(0xffffffffu, lp0, off);
        lp1 += __shfl_xor_sync(0xffffffffu, lp1, off);
    }
    if (t == 0) {
        red[nw * 64 + r0]     = lp0;
        red[nw * 64 + r0 + 8] = lp1;
    }

    // ---- O combine across nw pairs ----
    if (nw == 1) {
        #pragma unroll
        for (int nt2 = 0; nt2 < 4; nt2++) {
            int f = 8 * nt2 + 2 * t;
            *(float2*)&Osm[r0 * 32 + f]       = make_float2(o[nt2][0], o[nt2][1]);
            *(float2*)&Osm[(r0 + 8) * 32 + f] = make_float2(o[nt2][2], o[nt2][3]);
        }
    }
    __syncthreads();

    if (nw == 0) {
        float inv0 = 1.0f / (red[r0] + red[64 + r0]);
        float inv1 = 1.0f / (red[r0 + 8] + red[64 + r0 + 8]);
        int b = q0 / 4608;
        int rem = q0 - b * 4608;
        int h = rem / 576;
        int lp = (rem - h * 576) + 16 * mw + g;
        #pragma unroll
        for (int nt2 = 0; nt2 < 4; nt2++) {
            int f = 8 * nt2 + 2 * t;
            float2 pa = *(const float2*)&Osm[r0 * 32 + f];
            float2 pb = *(const float2*)&Osm[(r0 + 8) * 32 + f];
            size_t base = ((size_t)(b * 256 + h * 32 + f)) * 576;
            out[base + lp]           = (o[nt2][0] + pa.x) * inv0;
            out[base + 576 + lp]     = (o[nt2][1] + pa.y) * inv0;
            out[base + lp + 8]       = (o[nt2][2] + pb.x) * inv1;
            out[base + 576 + lp + 8] = (o[nt2][3] + pb.y) * inv1;
        }
    }
}

// ---------------------------------------------------------------------------
extern "C" void kernel_launch(void* const* d_in, const int* in_sizes, int n_in,
                              void* d_out, int out_size)
{
    const float* x  = (const float*)d_in[0];
    const float* wq = (const float*)d_in[1];
    const float* wk = (const float*)d_in[2];
    const float* wv = (const float*)d_in[3];
    float* out = (float*)d_out;

    static bool attr_set = false;
    if (!attr_set) {
        cudaFuncSetAttribute(attn_kernel,
                             cudaFuncAttributeMaxDynamicSharedMemorySize,
                             SMEM_BYTES);
        attr_set = true;
    }

    dim3 g1(16, 9);
    qkv_kernel<<<g1, 256>>>(x, wq, wk, wv);
    attn_kernel<<<NTOK / 64, 256, SMEM_BYTES>>>(out);
}

// round 8
// speedup vs baseline: 1.6191x; 1.1168x over previous
#include <cuda_runtime.h>
#include <cuda_fp16.h>
#include <math.h>

#define B_   2
#define G_   8
#define L_   576
#define D_   32
#define NTOK 9216
#define NT32 (NTOK * 32)
#define NTILES 144
#define LOG2E 1.4426950408889634f

// Scratch (__device__ globals; allocation-free rule)
__device__ float    g_Q[NT32];
__device__ unsigned g_Kq[NT32];       // f16 K: [tile][kn 64][8 uint4: (b0hi,b1hi,b0lo,b1lo) per (t,ks)]
__device__ unsigned g_Vp[NT32];       // tf32 V: [tile][kp 32][feat 32] uint2 = (V[key t],V[key t+4])
__device__ float    g_qnorm2[NTOK];
__device__ int      g_kmax2;

__device__ __forceinline__ unsigned f2tf32(float x) {
    unsigned r;
    asm("cvt.rna.tf32.f32 %0, %1;" : "=r"(r) : "f"(x));
    return r;
}
__device__ __forceinline__ void split2_f16(float x0, float x1,
                                           unsigned& hi, unsigned& lo) {
    __half h0 = __float2half_rn(x0), h1 = __float2half_rn(x1);
    __half l0 = __float2half_rn(x0 - __half2float(h0));
    __half l1 = __float2half_rn(x1 - __half2float(h1));
    hi = ((unsigned)__half_as_ushort(h1) << 16) | __half_as_ushort(h0);
    lo = ((unsigned)__half_as_ushort(l1) << 16) | __half_as_ushort(l0);
}
__device__ __forceinline__ void mma_f16(float c[4], const unsigned a[4],
                                        unsigned b0, unsigned b1) {
    asm volatile(
        "mma.sync.aligned.m16n8k16.row.col.f32.f16.f16.f32 "
        "{%0,%1,%2,%3}, {%4,%5,%6,%7}, {%8,%9}, {%0,%1,%2,%3};"
        : "+f"(c[0]), "+f"(c[1]), "+f"(c[2]), "+f"(c[3])
        : "r"(a[0]), "r"(a[1]), "r"(a[2]), "r"(a[3]), "r"(b0), "r"(b1));
}
__device__ __forceinline__ void mma_tf32(float c[4], const unsigned a[4],
                                         unsigned b0, unsigned b1) {
    asm volatile(
        "mma.sync.aligned.m16n8k8.row.col.f32.tf32.tf32.f32 "
        "{%0,%1,%2,%3}, {%4,%5,%6,%7}, {%8,%9}, {%0,%1,%2,%3};"
        : "+f"(c[0]), "+f"(c[1]), "+f"(c[2]), "+f"(c[3])
        : "r"(a[0]), "r"(a[1]), "r"(a[2]), "r"(a[3]), "r"(b0), "r"(b1));
}

// ---------------------------------------------------------------------------
// Kernel 1: grouped 1x1 conv. Q scaled + row norms. K(+PE) -> f16 hi/lo in the
// attn smem image (sigma-permuted keys). V -> tf32 paired layout.
// ---------------------------------------------------------------------------
__global__ void __launch_bounds__(256) qkv_kernel(
    const float* __restrict__ x,
    const float* __restrict__ wq,
    const float* __restrict__ wk,
    const float* __restrict__ wv)
{
    const int bh = blockIdx.x;
    const int b  = bh >> 3;
    const int h  = bh & 7;
    const int l0 = blockIdx.y * 64;

    __shared__ float xs[32][64];

    const int tid = threadIdx.x;
    const float* xbase = x + ((size_t)(b * 256 + h * 32)) * L_ + l0;
    for (int i = tid; i < 32 * 64; i += 256) {
        int dd = i >> 6, ll = i & 63;
        xs[dd][ll] = xbase[dd * L_ + ll];
    }
    __syncthreads();

    const int o    = tid & 31;           // output feature (dim)
    const int lg   = (tid >> 5) * 8;     // 8 local keys
    const int c    = h * 32 + o;
    const int nbase = bh * L_ + l0 + lg;
    const int tile = bh * 9 + blockIdx.y;

    #pragma unroll
    for (int m = 0; m < 3; m++) {
        const float* w = (m == 0 ? wq : (m == 1 ? wk : wv)) + (size_t)c * 32;
        float acc[8];
        #pragma unroll
        for (int e = 0; e < 8; e++) acc[e] = 0.f;

        #pragma unroll
        for (int dd = 0; dd < 32; dd++) {
            float wv_ = w[dd];
            float4 a  = *(const float4*)&xs[dd][lg];
            float4 a2 = *(const float4*)&xs[dd][lg + 4];
            acc[0] = fmaf(wv_, a.x,  acc[0]);
            acc[1] = fmaf(wv_, a.y,  acc[1]);
            acc[2] = fmaf(wv_, a.z,  acc[2]);
            acc[3] = fmaf(wv_, a.w,  acc[3]);
            acc[4] = fmaf(wv_, a2.x, acc[4]);
            acc[5] = fmaf(wv_, a2.y, acc[5]);
            acc[6] = fmaf(wv_, a2.z, acc[6]);
            acc[7] = fmaf(wv_, a2.w, acc[7]);
        }

        if (m == 0) {
            const float scale = 0.17677669529663688f;  // 1/sqrt(32)
            #pragma unroll
            for (int e = 0; e < 8; e++) {
                float val = acc[e] * scale;
                g_Q[(size_t)(nbase + e) * 32 + o] = val;
                float sq = val * val;
                #pragma unroll
                for (int off = 16; off > 0; off >>= 1)
                    sq += __shfl_xor_sync(0xffffffffu, sq, off);
                if (o == 0) g_qnorm2[nbase + e] = sq;
            }
        } else if (m == 1) {
            int ieven = c & ~1;
            float tf = (-9.210340371976184f * (float)ieven) * (1.0f / 256.0f);
            float invf = (float)exp((double)tf);
            // base angle + step via double sincos once; f32 recurrence over 8
            double s0d, c0d, sid, cid;
            sincos((double)invf * (double)(l0 + lg), &s0d, &c0d);
            sincos((double)invf, &sid, &cid);
            float sB = (float)s0d, cB = (float)c0d;
            float sI = (float)sid, cI = (float)cid;
            // f16 B-frag slot for this dim
            const int ksq  = o >> 4;             // k16 chunk
            const int rr   = o & 15;
            const int tq   = (rr & 7) >> 1;
            const int hw   = rr & 1;
            const int breg = rr >> 3;
            const int hbase = (2 * tq + ksq) * 8 + breg * 2 + hw;
            __half* Kh = (__half*)g_Kq;
            float kmax_local = 0.f;
            #pragma unroll
            for (int e = 0; e < 8; e++) {
                float pe = (c & 1) ? cB : sB;
                float sn = sB * cI + cB * sI;
                float cn = cB * cI - sB * sI;
                sB = sn; cB = cn;
                float val = acc[e] + pe;
                __half hh = __float2half_rn(val);
                __half hl = __float2half_rn(val - __half2float(hh));
                int j = lg + e;
                int kn = (j & 56) + 2 * (j & 3) + ((j >> 2) & 1);
                size_t hb = (size_t)tile * 4096 + (size_t)kn * 64 + hbase;
                Kh[hb]     = hh;
                Kh[hb + 4] = hl;
                float sq = val * val;
                #pragma unroll
                for (int off = 16; off > 0; off >>= 1)
                    sq += __shfl_xor_sync(0xffffffffu, sq, off);
                kmax_local = fmaxf(kmax_local, sq);
            }
            if (o == 0) atomicMax(&g_kmax2, __float_as_int(kmax_local));
        } else {
            #pragma unroll
            for (int e = 0; e < 8; e++) {
                int j = lg + e;
                int kp   = ((j >> 3) << 2) + (j & 3);
                int slot = (j >> 2) & 1;
                g_Vp[(size_t)tile * 2048 + (size_t)(kp * 32 + o) * 2 + slot] =
                    f2tf32(acc[e]);
            }
        }
    }
}

// ---------------------------------------------------------------------------
// Kernel 2: flash attention. QK: f16 m16n8k16 2-split (3 MMAs per chunk).
// PV: tf32 single-pass, P in registers via sigma-permutation.
// 144 blocks x 256 threads. K/V double-buffered, ONE __syncthreads per tile.
// ---------------------------------------------------------------------------
#define KSTR  36       // words per key: 8 uint4 + pad (144B, 16B mult; 36%32=4)
#define KBUF  2304     // 64 * 36
#define VSTRU 36       // uint2 per kp row
#define VBUF  2304     // 32 * 36 * 2 words
#define QSTR  36
#define OFF_K 0
#define OFF_V (2 * KBUF)
#define OFF_Q (OFF_V + 2 * VBUF)
#define OFF_O (OFF_Q + 64 * QSTR)
#define OFF_R (OFF_O + 2048)
#define SMEM_WORDS (OFF_R + 128)
#define SMEM_BYTES (SMEM_WORDS * 4)

__global__ void __launch_bounds__(256) attn_kernel(float* __restrict__ out)
{
    extern __shared__ unsigned smem[];
    unsigned* Ks  = smem + OFF_K;
    unsigned* Vs  = smem + OFF_V;
    float*    Qst = (float*)(smem + OFF_Q);
    float*    Osm = (float*)(smem + OFF_O);
    float*    red = (float*)(smem + OFF_R);

    const int tid  = threadIdx.x;
    const int lane = tid & 31;
    const int w    = tid >> 5;
    const int mw   = w >> 1, nw = w & 1;
    const int g    = lane >> 2, t = lane & 3;
    const int q0   = blockIdx.x * 64;
    const int r0   = 16 * mw + g;

    // ---- stage Q, build f16 split A-frags ----
    for (int i = tid; i < 512; i += 256) {
        int r = i >> 3, c = (i & 7) * 4;
        *(float4*)&Qst[r * QSTR + c] =
            *(const float4*)&g_Q[(size_t)(q0 + r) * 32 + c];
    }
    __syncthreads();

    unsigned qh[2][4], ql[2][4];
    #pragma unroll
    for (int ks = 0; ks < 2; ks++) {
        int d0 = 16 * ks + 2 * t;
        split2_f16(Qst[r0 * QSTR + d0],           Qst[r0 * QSTR + d0 + 1],
                   qh[ks][0], ql[ks][0]);
        split2_f16(Qst[(r0 + 8) * QSTR + d0],     Qst[(r0 + 8) * QSTR + d0 + 1],
                   qh[ks][1], ql[ks][1]);
        split2_f16(Qst[r0 * QSTR + d0 + 8],       Qst[r0 * QSTR + d0 + 9],
                   qh[ks][2], ql[ks][2]);
        split2_f16(Qst[(r0 + 8) * QSTR + d0 + 8], Qst[(r0 + 8) * QSTR + d0 + 9],
                   qh[ks][3], ql[ks][3]);
    }

    const float kmax2 = __int_as_float(g_kmax2);
    const float Ml0 = sqrtf(g_qnorm2[q0 + r0]     * kmax2) * LOG2E;
    const float Ml1 = sqrtf(g_qnorm2[q0 + r0 + 8] * kmax2) * LOG2E;

    // ---- prefetch tile 0 into buffer 0 ----
    {
        // K: 512 uint4/tile -> 2 per thread
        #pragma unroll
        for (int j = 0; j < 2; j++) {
            int u = tid + 256 * j;
            uint4 kv = *(const uint4*)&g_Kq[(size_t)u * 4];
            int kn = u >> 3, idx = u & 7;
            *(uint4*)&Ks[kn * KSTR + idx * 4] = kv;
        }
        // V: 512 uint4/tile -> 2 per thread
        #pragma unroll
        for (int j = 0; j < 2; j++) {
            int u = tid + 256 * j;
            uint4 vv = *(const uint4*)&g_Vp[(size_t)u * 4];
            int kp = u >> 4, fp = u & 15;
            *(uint4*)&Vs[kp * (2 * VSTRU) + fp * 4] = vv;
        }
    }
    __syncthreads();

    float o[4][4];
    #pragma unroll
    for (int i = 0; i < 4; i++)
        #pragma unroll
        for (int jj = 0; jj < 4; jj++) o[i][jj] = 0.f;
    float lp0 = 0.f, lp1 = 0.f;

    for (int tt = 0; tt < NTILES; tt++) {
        const unsigned* Kc = Ks + (tt & 1) * KBUF;
        const unsigned* Vc = Vs + (tt & 1) * VBUF;
        unsigned* Kn = Ks + ((tt + 1) & 1) * KBUF;
        unsigned* Vn = Vs + ((tt + 1) & 1) * VBUF;

        // ---- LDG tile tt+1 ----
        uint4 nk[2], nv[2];
        const bool has_next = (tt + 1 < NTILES);
        if (has_next) {
            size_t kb = (size_t)(tt + 1) * 2048;
            #pragma unroll
            for (int j = 0; j < 2; j++) {
                int u = tid + 256 * j;
                nk[j] = *(const uint4*)&g_Kq[kb + (size_t)u * 4];
                nv[j] = *(const uint4*)&g_Vp[kb + (size_t)u * 4];
            }
        }

        // ---- S = Q K^T : f16 k16, 3-term split ----
        float S[4][4];
        #pragma unroll
        for (int i = 0; i < 4; i++)
            #pragma unroll
            for (int jj = 0; jj < 4; jj++) S[i][jj] = 0.f;

        #pragma unroll
        for (int ks = 0; ks < 2; ks++) {
            #pragma unroll
            for (int nt = 0; nt < 4; nt++) {
                int kn = 32 * nw + 8 * nt + g;
                uint4 bf = *(const uint4*)&Kc[kn * KSTR + (2 * t + ks) * 4];
                mma_f16(S[nt], qh[ks], bf.x, bf.y);
                mma_f16(S[nt], ql[ks], bf.x, bf.y);
                mma_f16(S[nt], qh[ks], bf.z, bf.w);
            }
        }

        // ---- P = exp2(S*log2e - M) in registers; accumulate l ----
        float P[4][4];
        #pragma unroll
        for (int nt = 0; nt < 4; nt++) {
            P[nt][0] = exp2f(fmaf(S[nt][0], LOG2E, -Ml0));
            P[nt][1] = exp2f(fmaf(S[nt][1], LOG2E, -Ml0));
            P[nt][2] = exp2f(fmaf(S[nt][2], LOG2E, -Ml1));
            P[nt][3] = exp2f(fmaf(S[nt][3], LOG2E, -Ml1));
            lp0 += P[nt][0] + P[nt][1];
            lp1 += P[nt][2] + P[nt][3];
        }

        // ---- O += P V over this warp's 32 keys (tf32 single-pass) ----
        #pragma unroll
        for (int ks = 0; ks < 4; ks++) {
            unsigned a[4];
            a[0] = f2tf32(P[ks][0]);   // row r0,   k=t
            a[1] = f2tf32(P[ks][2]);   // row r0+8, k=t
            a[2] = f2tf32(P[ks][1]);   // row r0,   k=t+4
            a[3] = f2tf32(P[ks][3]);   // row r0+8, k=t+4
            int kp = (4 * nw + ks) * 4 + t;
            #pragma unroll
            for (int nt2 = 0; nt2 < 4; nt2++) {
                uint2 bv = *(const uint2*)&Vc[(kp * VSTRU + 8 * nt2 + g) * 2];
                mma_tf32(o[nt2], a, bv.x, bv.y);
            }
        }

        // ---- STS tile tt+1 ----
        if (has_next) {
            #pragma unroll
            for (int j = 0; j < 2; j++) {
                int u = tid + 256 * j;
                int kn = u >> 3, idx = u & 7;
                *(uint4*)&Kn[kn * KSTR + idx * 4] = nk[j];
                int kp = u >> 4, fp = u & 15;
                *(uint4*)&Vn[kp * (2 * VSTRU) + fp * 4] = nv[j];
            }
        }
        __syncthreads();   // the one barrier per tile
    }

    // ---- l reduction ----
    #pragma unroll
    for (int off = 1; off < 4; off <<= 1) {
        lp0 += __shfl_xor_sync(0xffffffffu, lp0, off);
        lp1 += __shfl_xor_sync(0xffffffffu, lp1, off);
    }
    if (t == 0) {
        red[nw * 64 + r0]     = lp0;
        red[nw * 64 + r0 + 8] = lp1;
    }

    // ---- O combine across nw pairs ----
    if (nw == 1) {
        #pragma unroll
        for (int nt2 = 0; nt2 < 4; nt2++) {
            int f = 8 * nt2 + 2 * t;
            *(float2*)&Osm[r0 * 32 + f]       = make_float2(o[nt2][0], o[nt2][1]);
            *(float2*)&Osm[(r0 + 8) * 32 + f] = make_float2(o[nt2][2], o[nt2][3]);
        }
    }
    __syncthreads();

    if (nw == 0) {
        float inv0 = 1.0f / (red[r0] + red[64 + r0]);
        float inv1 = 1.0f / (red[r0 + 8] + red[64 + r0 + 8]);
        int b = q0 / 4608;
        int rem = q0 - b * 4608;
        int h = rem / 576;
        int lp = (rem - h * 576) + 16 * mw + g;
        #pragma unroll
        for (int nt2 = 0; nt2 < 4; nt2++) {
            int f = 8 * nt2 + 2 * t;
            float2 pa = *(const float2*)&Osm[r0 * 32 + f];
            float2 pb = *(const float2*)&Osm[(r0 + 8) * 32 + f];
            size_t base = ((size_t)(b * 256 + h * 32 + f)) * 576;
            out[base + lp]           = (o[nt2][0] + pa.x) * inv0;
            out[base + 576 + lp]     = (o[nt2][1] + pa.y) * inv0;
            out[base + lp + 8]       = (o[nt2][2] + pb.x) * inv1;
            out[base + 576 + lp + 8] = (o[nt2][3] + pb.y) * inv1;
        }
    }
}

// ---------------------------------------------------------------------------
extern "C" void kernel_launch(void* const* d_in, const int* in_sizes, int n_in,
                              void* d_out, int out_size)
{
    const float* x  = (const float*)d_in[0];
    const float* wq = (const float*)d_in[1];
    const float* wk = (const float*)d_in[2];
    const float* wv = (const float*)d_in[3];
    float* out = (float*)d_out;

    static bool attr_set = false;
    if (!attr_set) {
        cudaFuncSetAttribute(attn_kernel,
                             cudaFuncAttributeMaxDynamicSharedMemorySize,
                             SMEM_BYTES);
        attr_set = true;
    }

    dim3 g1(16, 9);
    qkv_kernel<<<g1, 256>>>(x, wq, wk, wv);
    attn_kernel<<<NTOK / 64, 256, SMEM_BYTES>>>(out);
}